// round 3
// baseline (speedup 1.0000x reference)
#include <cuda_runtime.h>
#include <math.h>

// ---------------- problem constants ----------------
static constexpr int H_   = 2048;   // hidden
static constexpr int IM_  = 1024;   // routed intermediate
static constexpr int IS_  = 2048;   // shared intermediate
static constexpr int E_   = 16;     // experts
static constexpr int K_   = 8;      // top-k
static constexpr int TMAX = 2048;   // tokens
static constexpr float SCALE_ = 2.5f;

// ---------------- scratch (device globals: no allocation) ----------------
__device__ float g_Ps[(size_t)TMAX * IS_];          // 16 MB  shared-expert intermediate
__device__ float g_Pr[(size_t)E_ * TMAX * IM_];     // 128 MB routed intermediate (per expert, per slot)
__device__ int   g_cnt[E_];
__device__ int   g_tok[E_ * TMAX];
__device__ float g_wt [E_ * TMAX];

// ---------------- counter reset ----------------
__global__ void zero_cnt_kernel() {
    if (threadIdx.x < E_) g_cnt[threadIdx.x] = 0;
}

// ---------------- router: sigmoid + top-8 + normalize, append to expert lists ----------------
__global__ void router_kernel(const float* __restrict__ X,
                              const float* __restrict__ gw,
                              int T) {
    int gtid = blockIdx.x * blockDim.x + threadIdx.x;
    int t    = gtid >> 5;
    int lane = gtid & 31;
    if (t >= T) return;

    const float* h = X + (size_t)t * H_;
    float acc[E_];
#pragma unroll
    for (int e = 0; e < E_; e++) acc[e] = 0.f;

    for (int i = lane; i < H_; i += 32) {
        float hv = h[i];
#pragma unroll
        for (int e = 0; e < E_; e++) acc[e] += hv * gw[e * H_ + i];
    }
#pragma unroll
    for (int e = 0; e < E_; e++) {
#pragma unroll
        for (int o = 16; o > 0; o >>= 1)
            acc[e] += __shfl_xor_sync(0xffffffffu, acc[e], o);
    }

    if (lane == 0) {
        float w[E_];
#pragma unroll
        for (int e = 0; e < E_; e++) w[e] = 1.f / (1.f + expf(-acc[e]));

        int   sel[K_];
        float sv[K_];
        bool  used[E_] = {};
        float sum = 0.f;
        for (int k = 0; k < K_; k++) {
            int best = 0; float bv = -1.f;
            for (int e = 0; e < E_; e++)
                if (!used[e] && w[e] > bv) { bv = w[e]; best = e; }
            used[best] = true;
            sel[k] = best; sv[k] = bv; sum += bv;
        }
        float norm = SCALE_ / (sum + 1e-6f);
        for (int k = 0; k < K_; k++) {
            int e = sel[k];
            int p = atomicAdd(&g_cnt[e], 1);
            g_tok[e * TMAX + p] = t;
            g_wt [e * TMAX + p] = sv[k] * norm;
        }
    }
}

// ---------------- up-proj: P = silu(A@Wg) * (A@Wu) [* comb weight] ----------------
// 64x64 tile, BK=16, 256 threads, 4x4 microtile, dual-B (shares the A tile).
template <bool GATHER>
__launch_bounds__(256)
__global__ void up_kernel(const float* __restrict__ X,
                          const float* __restrict__ Wg_g,
                          const float* __restrict__ Wu_g,
                          int N, int T) {
    const int e    = GATHER ? blockIdx.z : 0;
    const int rows = GATHER ? g_cnt[e] : T;
    const int row0 = blockIdx.y * 64;
    if (row0 >= rows) return;
    const int col0 = blockIdx.x * 64;

    const float* Wg = Wg_g + (size_t)e * H_ * N;
    const float* Wu = Wu_g + (size_t)e * H_ * N;
    float* P = GATHER ? (g_Pr + (size_t)e * TMAX * N) : g_Ps;

    __shared__ float As[64][20];
    __shared__ float Bg[16][64];
    __shared__ float Bu[16][64];
    __shared__ int   s_tok[64];
    __shared__ float s_wt[64];

    const int tid = threadIdx.x;
    if (tid < 64) {
        int slot = row0 + tid;
        int cs = slot < rows ? slot : rows - 1;
        if (GATHER) {
            s_tok[tid] = g_tok[e * TMAX + cs];
            s_wt[tid]  = g_wt [e * TMAX + cs];
        } else {
            s_tok[tid] = cs;
        }
    }
    __syncthreads();

    const int am = tid >> 2, ak = (tid & 3) << 2;   // A loader: row, k-offset
    const int bk = tid >> 4, bn = (tid & 15) << 2;  // B loader: k, n-offset
    const float* arow = X + (size_t)s_tok[am] * H_ + ak;
    const float* bgp  = Wg + (size_t)bk * N + col0 + bn;
    const float* bup  = Wu + (size_t)bk * N + col0 + bn;

    const int tx = tid & 15, ty = tid >> 4;
    float accg[4][4] = {}, accu[4][4] = {};

    for (int k0 = 0; k0 < H_; k0 += 16) {
        float4 av = *(const float4*)(arow + k0);
        float4 g4 = *(const float4*)(bgp + (size_t)k0 * N);
        float4 u4 = *(const float4*)(bup + (size_t)k0 * N);
        *(float4*)&As[am][ak] = av;
        *(float4*)&Bg[bk][bn] = g4;
        *(float4*)&Bu[bk][bn] = u4;
        __syncthreads();
#pragma unroll
        for (int kk = 0; kk < 16; kk++) {
            float4 bg = *(const float4*)&Bg[kk][tx << 2];
            float4 bu = *(const float4*)&Bu[kk][tx << 2];
#pragma unroll
            for (int i = 0; i < 4; i++) {
                float a = As[(ty << 2) + i][kk];
                accg[i][0] += a * bg.x; accg[i][1] += a * bg.y;
                accg[i][2] += a * bg.z; accg[i][3] += a * bg.w;
                accu[i][0] += a * bu.x; accu[i][1] += a * bu.y;
                accu[i][2] += a * bu.z; accu[i][3] += a * bu.w;
            }
        }
        __syncthreads();
    }

#pragma unroll
    for (int i = 0; i < 4; i++) {
        int slot = row0 + (ty << 2) + i;
        if (slot < rows) {
            float w = GATHER ? s_wt[(ty << 2) + i] : 1.f;
            float* prow = P + (size_t)slot * N + col0 + (tx << 2);
#pragma unroll
            for (int j = 0; j < 4; j++) {
                float g = accg[i][j], u = accu[i][j];
                float s = g / (1.f + __expf(-g));   // silu
                prow[j] = s * u * w;
            }
        }
    }
}

// ---------------- down-proj: out (+)= P @ Wd ----------------
// GATHER: atomicAdd scatter to token rows.  !GATHER: plain store (initializes out).
template <bool GATHER>
__launch_bounds__(256)
__global__ void down_kernel(const float* __restrict__ Wd_g,
                            float* __restrict__ out,
                            int Kd, int T) {
    const int e    = GATHER ? blockIdx.z : 0;
    const int rows = GATHER ? g_cnt[e] : T;
    const int row0 = blockIdx.y * 64;
    if (row0 >= rows) return;
    const int col0 = blockIdx.x * 64;

    const float* Wd = Wd_g + (size_t)e * Kd * H_;
    const float* P  = GATHER ? (g_Pr + (size_t)e * TMAX * Kd) : g_Ps;

    __shared__ float As[64][20];
    __shared__ float Bs[16][64];
    __shared__ int   s_tok[64];
    __shared__ int   s_slot[64];

    const int tid = threadIdx.x;
    if (tid < 64) {
        int slot = row0 + tid;
        int cs = slot < rows ? slot : rows - 1;
        s_slot[tid] = cs;
        s_tok[tid]  = GATHER ? g_tok[e * TMAX + cs] : cs;
    }
    __syncthreads();

    const int am = tid >> 2, ak = (tid & 3) << 2;
    const int bk = tid >> 4, bn = (tid & 15) << 2;
    const float* arow = P + (size_t)s_slot[am] * Kd + ak;
    const float* bp   = Wd + (size_t)bk * H_ + col0 + bn;

    const int tx = tid & 15, ty = tid >> 4;
    float acc[4][4] = {};

    for (int k0 = 0; k0 < Kd; k0 += 16) {
        float4 av = *(const float4*)(arow + k0);
        float4 b4 = *(const float4*)(bp + (size_t)k0 * H_);
        *(float4*)&As[am][ak] = av;
        *(float4*)&Bs[bk][bn] = b4;
        __syncthreads();
#pragma unroll
        for (int kk = 0; kk < 16; kk++) {
            float4 b = *(const float4*)&Bs[kk][tx << 2];
#pragma unroll
            for (int i = 0; i < 4; i++) {
                float a = As[(ty << 2) + i][kk];
                acc[i][0] += a * b.x; acc[i][1] += a * b.y;
                acc[i][2] += a * b.z; acc[i][3] += a * b.w;
            }
        }
        __syncthreads();
    }

#pragma unroll
    for (int i = 0; i < 4; i++) {
        int slot = row0 + (ty << 2) + i;
        if (slot < rows) {
            int t = s_tok[(ty << 2) + i];
            float* orow = out + (size_t)t * H_ + col0 + (tx << 2);
#pragma unroll
            for (int j = 0; j < 4; j++) {
                if (GATHER) atomicAdd(&orow[j], acc[i][j]);
                else        orow[j] = acc[i][j];
            }
        }
    }
}

// ---------------- launch ----------------
extern "C" void kernel_launch(void* const* d_in, const int* in_sizes, int n_in,
                              void* d_out, int out_size) {
    const float* X   = (const float*)d_in[0];  // [T, H]
    const float* gw  = (const float*)d_in[1];  // [E, H]
    const float* Wg  = (const float*)d_in[2];  // [E, H, IM]
    const float* Wu  = (const float*)d_in[3];  // [E, H, IM]
    const float* Wd  = (const float*)d_in[4];  // [E, IM, H]
    const float* sWg = (const float*)d_in[5];  // [H, IS]
    const float* sWu = (const float*)d_in[6];  // [H, IS]
    const float* sWd = (const float*)d_in[7];  // [IS, H]
    float* out = (float*)d_out;

    int T = in_sizes[0] / H_;   // 2048

    // 1. reset per-expert counters
    zero_cnt_kernel<<<1, 32>>>();
    // 2. routing (1 warp / token)
    router_kernel<<<(T + 7) / 8, 256>>>(X, gw, T);
    // 3. shared-expert up-proj (SwiGLU) -> g_Ps
    up_kernel<false><<<dim3(IS_ / 64, (T + 63) / 64), 256>>>(X, sWg, sWu, IS_, T);
    // 4. routed up-proj (gathered, weight folded in) -> g_Pr
    up_kernel<true><<<dim3(IM_ / 64, (T + 63) / 64, E_), 256>>>(X, Wg, Wu, IM_, T);
    // 5. shared-expert down-proj: plain store, initializes every out element
    down_kernel<false><<<dim3(H_ / 64, (T + 63) / 64), 256>>>(sWd, out, IS_, T);
    // 6. routed down-proj: scatter atomicAdd on top
    down_kernel<true><<<dim3(H_ / 64, (T + 63) / 64, E_), 256>>>(Wd, out, IM_, T);
}

// round 5
// speedup vs baseline: 1.0001x; 1.0001x over previous
#include <cuda_runtime.h>
#include <math.h>

// ---------------- problem constants ----------------
static constexpr int H_   = 2048;   // hidden
static constexpr int IM_  = 1024;   // routed intermediate
static constexpr int IS_  = 2048;   // shared intermediate
static constexpr int E_   = 16;     // experts
static constexpr int K_   = 8;      // top-k
static constexpr int TMAX = 2048;   // tokens
static constexpr float SCALE_ = 2.5f;

// ---------------- scratch (device globals: no allocation) ----------------
__device__ float g_Ps[(size_t)TMAX * IS_];          // 16 MB  shared-expert intermediate
__device__ float g_Pr[(size_t)E_ * TMAX * IM_];     // 128 MB routed intermediate (per expert, per slot)
__device__ int   g_cnt[E_];
__device__ int   g_tok[E_ * TMAX];
__device__ float g_wt [E_ * TMAX];

// ---------------- counter reset ----------------
__global__ void zero_cnt_kernel() {
    if (threadIdx.x < E_) g_cnt[threadIdx.x] = 0;
}

// ---------------- router: sigmoid + top-8 + normalize, append to expert lists ----------------
__global__ void router_kernel(const float* __restrict__ X,
                              const float* __restrict__ gw,
                              int T) {
    int gtid = blockIdx.x * blockDim.x + threadIdx.x;
    int t    = gtid >> 5;
    int lane = gtid & 31;
    if (t >= T) return;

    const float* h = X + (size_t)t * H_;
    float acc[E_];
#pragma unroll
    for (int e = 0; e < E_; e++) acc[e] = 0.f;

    for (int i = lane; i < H_; i += 32) {
        float hv = h[i];
#pragma unroll
        for (int e = 0; e < E_; e++) acc[e] += hv * gw[e * H_ + i];
    }
#pragma unroll
    for (int e = 0; e < E_; e++) {
#pragma unroll
        for (int o = 16; o > 0; o >>= 1)
            acc[e] += __shfl_xor_sync(0xffffffffu, acc[e], o);
    }

    if (lane == 0) {
        float w[E_];
#pragma unroll
        for (int e = 0; e < E_; e++) w[e] = 1.f / (1.f + expf(-acc[e]));

        int   sel[K_];
        float sv[K_];
        bool  used[E_] = {};
        float sum = 0.f;
        for (int k = 0; k < K_; k++) {
            int best = 0; float bv = -1.f;
            for (int e = 0; e < E_; e++)
                if (!used[e] && w[e] > bv) { bv = w[e]; best = e; }
            used[best] = true;
            sel[k] = best; sv[k] = bv; sum += bv;
        }
        float norm = SCALE_ / (sum + 1e-6f);
        for (int k = 0; k < K_; k++) {
            int e = sel[k];
            int p = atomicAdd(&g_cnt[e], 1);
            g_tok[e * TMAX + p] = t;
            g_wt [e * TMAX + p] = sv[k] * norm;
        }
    }
}

// ---------------- up-proj: P = silu(A@Wg) * (A@Wu) [* comb weight] ----------------
// 64x64 tile, BK=16, 256 threads, 4x4 microtile, dual-B (shares the A tile).
template <bool GATHER>
__launch_bounds__(256)
__global__ void up_kernel(const float* __restrict__ X,
                          const float* __restrict__ Wg_g,
                          const float* __restrict__ Wu_g,
                          int N, int T) {
    const int e    = GATHER ? blockIdx.z : 0;
    const int rows = GATHER ? g_cnt[e] : T;
    const int row0 = blockIdx.y * 64;
    if (row0 >= rows) return;
    const int col0 = blockIdx.x * 64;

    const float* Wg = Wg_g + (size_t)e * H_ * N;
    const float* Wu = Wu_g + (size_t)e * H_ * N;
    float* P = GATHER ? (g_Pr + (size_t)e * TMAX * N) : g_Ps;

    __shared__ float As[64][20];
    __shared__ float Bg[16][64];
    __shared__ float Bu[16][64];
    __shared__ int   s_tok[64];
    __shared__ float s_wt[64];

    const int tid = threadIdx.x;
    if (tid < 64) {
        int slot = row0 + tid;
        int cs = slot < rows ? slot : rows - 1;
        if (GATHER) {
            s_tok[tid] = g_tok[e * TMAX + cs];
            s_wt[tid]  = g_wt [e * TMAX + cs];
        } else {
            s_tok[tid] = cs;
        }
    }
    __syncthreads();

    const int am = tid >> 2, ak = (tid & 3) << 2;   // A loader: row, k-offset
    const int bk = tid >> 4, bn = (tid & 15) << 2;  // B loader: k, n-offset
    const float* arow = X + (size_t)s_tok[am] * H_ + ak;
    const float* bgp  = Wg + (size_t)bk * N + col0 + bn;
    const float* bup  = Wu + (size_t)bk * N + col0 + bn;

    const int tx = tid & 15, ty = tid >> 4;
    float accg[4][4] = {}, accu[4][4] = {};

    for (int k0 = 0; k0 < H_; k0 += 16) {
        float4 av = *(const float4*)(arow + k0);
        float4 g4 = *(const float4*)(bgp + (size_t)k0 * N);
        float4 u4 = *(const float4*)(bup + (size_t)k0 * N);
        *(float4*)&As[am][ak] = av;
        *(float4*)&Bg[bk][bn] = g4;
        *(float4*)&Bu[bk][bn] = u4;
        __syncthreads();
#pragma unroll
        for (int kk = 0; kk < 16; kk++) {
            float4 bg = *(const float4*)&Bg[kk][tx << 2];
            float4 bu = *(const float4*)&Bu[kk][tx << 2];
#pragma unroll
            for (int i = 0; i < 4; i++) {
                float a = As[(ty << 2) + i][kk];
                accg[i][0] += a * bg.x; accg[i][1] += a * bg.y;
                accg[i][2] += a * bg.z; accg[i][3] += a * bg.w;
                accu[i][0] += a * bu.x; accu[i][1] += a * bu.y;
                accu[i][2] += a * bu.z; accu[i][3] += a * bu.w;
            }
        }
        __syncthreads();
    }

#pragma unroll
    for (int i = 0; i < 4; i++) {
        int slot = row0 + (ty << 2) + i;
        if (slot < rows) {
            float w = GATHER ? s_wt[(ty << 2) + i] : 1.f;
            float* prow = P + (size_t)slot * N + col0 + (tx << 2);
#pragma unroll
            for (int j = 0; j < 4; j++) {
                float g = accg[i][j], u = accu[i][j];
                float s = g / (1.f + __expf(-g));   // silu
                prow[j] = s * u * w;
            }
        }
    }
}

// ---------------- down-proj: out (+)= P @ Wd ----------------
// GATHER: atomicAdd scatter to token rows.  !GATHER: plain store (initializes out).
template <bool GATHER>
__launch_bounds__(256)
__global__ void down_kernel(const float* __restrict__ Wd_g,
                            float* __restrict__ out,
                            int Kd, int T) {
    const int e    = GATHER ? blockIdx.z : 0;
    const int rows = GATHER ? g_cnt[e] : T;
    const int row0 = blockIdx.y * 64;
    if (row0 >= rows) return;
    const int col0 = blockIdx.x * 64;

    const float* Wd = Wd_g + (size_t)e * Kd * H_;
    const float* P  = GATHER ? (g_Pr + (size_t)e * TMAX * Kd) : g_Ps;

    __shared__ float As[64][20];
    __shared__ float Bs[16][64];
    __shared__ int   s_tok[64];
    __shared__ int   s_slot[64];

    const int tid = threadIdx.x;
    if (tid < 64) {
        int slot = row0 + tid;
        int cs = slot < rows ? slot : rows - 1;
        s_slot[tid] = cs;
        s_tok[tid]  = GATHER ? g_tok[e * TMAX + cs] : cs;
    }
    __syncthreads();

    const int am = tid >> 2, ak = (tid & 3) << 2;
    const int bk = tid >> 4, bn = (tid & 15) << 2;
    const float* arow = P + (size_t)s_slot[am] * Kd + ak;
    const float* bp   = Wd + (size_t)bk * H_ + col0 + bn;

    const int tx = tid & 15, ty = tid >> 4;
    float acc[4][4] = {};

    for (int k0 = 0; k0 < Kd; k0 += 16) {
        float4 av = *(const float4*)(arow + k0);
        float4 b4 = *(const float4*)(bp + (size_t)k0 * H_);
        *(float4*)&As[am][ak] = av;
        *(float4*)&Bs[bk][bn] = b4;
        __syncthreads();
#pragma unroll
        for (int kk = 0; kk < 16; kk++) {
            float4 b = *(const float4*)&Bs[kk][tx << 2];
#pragma unroll
            for (int i = 0; i < 4; i++) {
                float a = As[(ty << 2) + i][kk];
                acc[i][0] += a * b.x; acc[i][1] += a * b.y;
                acc[i][2] += a * b.z; acc[i][3] += a * b.w;
            }
        }
        __syncthreads();
    }

#pragma unroll
    for (int i = 0; i < 4; i++) {
        int slot = row0 + (ty << 2) + i;
        if (slot < rows) {
            int t = s_tok[(ty << 2) + i];
            float* orow = out + (size_t)t * H_ + col0 + (tx << 2);
#pragma unroll
            for (int j = 0; j < 4; j++) {
                if (GATHER) atomicAdd(&orow[j], acc[i][j]);
                else        orow[j] = acc[i][j];
            }
        }
    }
}

// ---------------- launch ----------------
extern "C" void kernel_launch(void* const* d_in, const int* in_sizes, int n_in,
                              void* d_out, int out_size) {
    const float* X   = (const float*)d_in[0];  // [T, H]
    const float* gw  = (const float*)d_in[1];  // [E, H]
    const float* Wg  = (const float*)d_in[2];  // [E, H, IM]
    const float* Wu  = (const float*)d_in[3];  // [E, H, IM]
    const float* Wd  = (const float*)d_in[4];  // [E, IM, H]
    const float* sWg = (const float*)d_in[5];  // [H, IS]
    const float* sWu = (const float*)d_in[6];  // [H, IS]
    const float* sWd = (const float*)d_in[7];  // [IS, H]
    float* out = (float*)d_out;

    int T = in_sizes[0] / H_;   // 2048

    // 1. reset per-expert counters
    zero_cnt_kernel<<<1, 32>>>();
    // 2. routing (1 warp / token)
    router_kernel<<<(T + 7) / 8, 256>>>(X, gw, T);
    // 3. shared-expert up-proj (SwiGLU) -> g_Ps
    up_kernel<false><<<dim3(IS_ / 64, (T + 63) / 64), 256>>>(X, sWg, sWu, IS_, T);
    // 4. routed up-proj (gathered, weight folded in) -> g_Pr
    up_kernel<true><<<dim3(IM_ / 64, (T + 63) / 64, E_), 256>>>(X, Wg, Wu, IM_, T);
    // 5. shared-expert down-proj: plain store, initializes every out element
    down_kernel<false><<<dim3(H_ / 64, (T + 63) / 64), 256>>>(sWd, out, IS_, T);
    // 6. routed down-proj: scatter atomicAdd on top
    down_kernel<true><<<dim3(H_ / 64, (T + 63) / 64, E_), 256>>>(Wd, out, IM_, T);
}

// round 7
// speedup vs baseline: 1.0319x; 1.0319x over previous
#include <cuda_runtime.h>
#include <cstdint>
#include <math.h>

static constexpr int H_   = 2048;
static constexpr int IM_  = 1024;
static constexpr int IS_  = 2048;
static constexpr int E_   = 16;
static constexpr int K_   = 8;
static constexpr int TMAX = 2048;
static constexpr float SCALE_ = 2.5f;

__device__ float g_Ps[(size_t)TMAX * IS_];
__device__ float g_Pr[(size_t)E_ * TMAX * IM_];
__device__ int   g_cnt[E_];
__device__ int   g_tok[E_ * TMAX];
__device__ float g_wt [E_ * TMAX];

// ---------------- helpers ----------------
__device__ __forceinline__ uint32_t smem_u32(const void* p) {
    uint32_t a;
    asm("{ .reg .u64 t; cvta.to.shared.u64 t, %1; cvt.u32.u64 %0, t; }" : "=r"(a) : "l"(p));
    return a;
}
__device__ __forceinline__ uint32_t sw128(uint32_t o) { return o ^ ((o >> 3) & 0x70); }

// split (x0,x1) into packed bf16x2 hi + bf16x2 lo (x0 in low half)
__device__ __forceinline__ void splitpair(float x0, float x1, uint32_t& hi, uint32_t& lo) {
    asm("cvt.rn.bf16x2.f32 %0, %1, %2;" : "=r"(hi) : "f"(x1), "f"(x0));
    float h0 = __uint_as_float(hi << 16);
    float h1 = __uint_as_float(hi & 0xffff0000u);
    float l0 = x0 - h0, l1 = x1 - h1;
    asm("cvt.rn.bf16x2.f32 %0, %1, %2;" : "=r"(lo) : "f"(l1), "f"(l0));
}
__device__ __forceinline__ void sts64(uint32_t a, uint32_t x, uint32_t y) {
    asm volatile("st.shared.v2.b32 [%0], {%1,%2};" :: "r"(a), "r"(x), "r"(y));
}
__device__ __forceinline__ void ldsm4(uint32_t addr, uint32_t* r) {
    asm volatile("ldmatrix.sync.aligned.m8n8.x4.shared.b16 {%0,%1,%2,%3}, [%4];"
        : "=r"(r[0]), "=r"(r[1]), "=r"(r[2]), "=r"(r[3]) : "r"(addr));
}
__device__ __forceinline__ void ldsm4t(uint32_t addr, uint32_t* r) {
    asm volatile("ldmatrix.sync.aligned.m8n8.x4.trans.shared.b16 {%0,%1,%2,%3}, [%4];"
        : "=r"(r[0]), "=r"(r[1]), "=r"(r[2]), "=r"(r[3]) : "r"(addr));
}
// D += A * B  (m16n8k16, bf16 in, fp32 acc)
__device__ __forceinline__ void mma16816(float* d, const uint32_t* a, const uint32_t* b) {
    asm volatile("mma.sync.aligned.m16n8k16.row.col.f32.bf16.bf16.f32 "
        "{%0,%1,%2,%3}, {%4,%5,%6,%7}, {%8,%9}, {%0,%1,%2,%3};"
        : "+f"(d[0]), "+f"(d[1]), "+f"(d[2]), "+f"(d[3])
        : "r"(a[0]), "r"(a[1]), "r"(a[2]), "r"(a[3]), "r"(b[0]), "r"(b[1]));
}

// smem layout (dynamic)
static constexpr int SM_TOK = 0;                    // 128 ints
static constexpr int SM_WT  = 512;                  // 128 floats
static constexpr int SM_A_H = 1024;                 // 128 rows x 128B
static constexpr int SM_A_L = SM_A_H + 16384;
static constexpr int SM_B_H = SM_A_L + 16384;       // 64 rows x 128B
static constexpr int SM_B_L = SM_B_H + 8192;
static constexpr int SMEM_BYTES = SM_B_L + 8192;    // 50176

__global__ void zero_cnt_kernel() { if (threadIdx.x < E_) g_cnt[threadIdx.x] = 0; }

__global__ void router_kernel(const float* __restrict__ X, const float* __restrict__ gw, int T) {
    int gtid = blockIdx.x * blockDim.x + threadIdx.x;
    int t = gtid >> 5, lane = gtid & 31;
    if (t >= T) return;
    const float* h = X + (size_t)t * H_;
    float acc[E_];
#pragma unroll
    for (int e = 0; e < E_; e++) acc[e] = 0.f;
    for (int i = lane; i < H_; i += 32) {
        float hv = h[i];
#pragma unroll
        for (int e = 0; e < E_; e++) acc[e] += hv * gw[e * H_ + i];
    }
#pragma unroll
    for (int e = 0; e < E_; e++)
#pragma unroll
        for (int o = 16; o > 0; o >>= 1) acc[e] += __shfl_xor_sync(0xffffffffu, acc[e], o);
    if (lane == 0) {
        float w[E_];
#pragma unroll
        for (int e = 0; e < E_; e++) w[e] = 1.f / (1.f + expf(-acc[e]));
        bool used[E_] = {};
        int sel[K_]; float sv[K_]; float sum = 0.f;
        for (int k = 0; k < K_; k++) {
            int best = 0; float bv = -1.f;
            for (int e = 0; e < E_; e++)
                if (!used[e] && w[e] > bv) { bv = w[e]; best = e; }
            used[best] = true; sel[k] = best; sv[k] = bv; sum += bv;
        }
        float norm = SCALE_ / (sum + 1e-6f);
        for (int k = 0; k < K_; k++) {
            int e = sel[k];
            int p = atomicAdd(&g_cnt[e], 1);
            g_tok[e * TMAX + p] = t;
            g_wt [e * TMAX + p] = sv[k] * norm;
        }
    }
}

// ===== up: P = silu(A@Wg)*(A@Wu)[*w] — CTA tile M=128 x N=32 (per matrix), split-bf16 mma.sync =====
template <bool GATHER>
__global__ void __launch_bounds__(256, 2)
up_mma(const float* __restrict__ X, const float* __restrict__ Wg_g,
       const float* __restrict__ Wu_g, int N, int T) {
    const int e    = GATHER ? blockIdx.z : 0;
    const int rows = GATHER ? g_cnt[e] : T;
    const int row0 = blockIdx.y * 128;
    if (row0 >= rows) return;
    const int col0 = blockIdx.x * 32;
    const float* Wg = Wg_g + (size_t)e * H_ * N;
    const float* Wu = Wu_g + (size_t)e * H_ * N;
    float* P = GATHER ? (g_Pr + (size_t)e * TMAX * N) : g_Ps;

    extern __shared__ char smem[];
    uint32_t sb = smem_u32(smem);
    const int tid = threadIdx.x, wid = tid >> 5, lane = tid & 31;
    int*   s_tok = (int*)(smem + SM_TOK);
    float* s_wt  = (float*)(smem + SM_WT);

    if (tid < 128) {
        int slot = row0 + tid;
        int cs = slot < rows ? slot : rows - 1;
        if (GATHER) { s_tok[tid] = g_tok[e * TMAX + cs]; s_wt[tid] = g_wt[e * TMAX + cs]; }
        else        { s_tok[tid] = cs; }
    }
    __syncthreads();

    // A loader: 2 threads per row
    const int am = tid >> 1, ah = tid & 1;
    const size_t aoff = (size_t)s_tok[am] * H_ + ah * 32;
    const uint32_t abase = am * 128 + ah * 64;
    // B loader: row = tid>>3 (+32), fi = tid&7 -> n0 = fi*4 (32 n per matrix)
    const int brow = tid >> 3, bn0 = (tid & 7) * 4;

    // fragment addressing (constant per thread)
    const int wm = wid & 3, wn = wid >> 2;          // m-block, n-half(16)
    const int a_r  = wm * 32 + (lane & 15);
    const uint32_t xorA = (a_r & 7) << 4;
    const uint32_t a_hi16 = (lane >> 4) * 16;
    const int b_r  = lane & 15;
    const uint32_t xorB = (b_r & 7) << 4;
    const uint32_t nbG = wn * 32 + a_hi16;          // byte-in-row for G frag
    const uint32_t nbU = nbG + 64;                  // U matrix at +64B

    float accg[2][2][4] = {}, accu[2][2][4] = {};

    const int NCH = H_ / 64;
    for (int ch = 0; ch < NCH; ch++) {
        const int k0g = ch * 64;
        // ---- A tile: 128x64 split to hi/lo, sw128
        {
            const float* ap = X + aoff + k0g;
#pragma unroll
            for (int i = 0; i < 8; i++) {
                float4 v = *(const float4*)(ap + i * 4);
                uint32_t h0, l0, h1, l1;
                splitpair(v.x, v.y, h0, l0);
                splitpair(v.z, v.w, h1, l1);
                uint32_t sw = sw128(abase + i * 8);
                sts64(sb + SM_A_H + sw, h0, h1);
                sts64(sb + SM_A_L + sw, l0, l1);
            }
        }
        // ---- B tiles: rows k, bytes [0:64)=G [64:128)=U, split hi/lo
        {
#pragma unroll
            for (int p = 0; p < 2; p++) {
                int r = brow + p * 32;
                const float* pg = Wg + (size_t)(k0g + r) * N + col0 + bn0;
                const float* pu = Wu + (size_t)(k0g + r) * N + col0 + bn0;
                float4 vg = *(const float4*)pg;
                float4 vu = *(const float4*)pu;
                uint32_t h0, l0, h1, l1;
                splitpair(vg.x, vg.y, h0, l0);
                splitpair(vg.z, vg.w, h1, l1);
                uint32_t swg = sw128(r * 128 + bn0 * 2);
                sts64(sb + SM_B_H + swg, h0, h1);
                sts64(sb + SM_B_L + swg, l0, l1);
                splitpair(vu.x, vu.y, h0, l0);
                splitpair(vu.z, vu.w, h1, l1);
                uint32_t swu = sw128(r * 128 + 64 + bn0 * 2);
                sts64(sb + SM_B_H + swu, h0, h1);
                sts64(sb + SM_B_L + swu, l0, l1);
            }
        }
        __syncthreads();

        // ---- compute 4 k16 steps
#pragma unroll
        for (int ks = 0; ks < 4; ks++) {
            const uint32_t kb = ks * 32;
            uint32_t Ah[2][4], Al[2][4];
#pragma unroll
            for (int mi = 0; mi < 2; mi++) {
                uint32_t ra = (uint32_t)(a_r + mi * 16) * 128 + ((kb + a_hi16) ^ xorA);
                ldsm4(sb + SM_A_H + ra, Ah[mi]);
                ldsm4(sb + SM_A_L + ra, Al[mi]);
            }
            uint32_t rb = (uint32_t)(ks * 16 + b_r) * 128;
            uint32_t Bgh[4], Bgl[4], Buh[4], Bul[4];
            ldsm4t(sb + SM_B_H + rb + (nbG ^ xorB), Bgh);
            ldsm4t(sb + SM_B_L + rb + (nbG ^ xorB), Bgl);
            ldsm4t(sb + SM_B_H + rb + (nbU ^ xorB), Buh);
            ldsm4t(sb + SM_B_L + rb + (nbU ^ xorB), Bul);
#pragma unroll
            for (int mi = 0; mi < 2; mi++) {
#pragma unroll
                for (int nj = 0; nj < 2; nj++) {
                    mma16816(accg[mi][nj], Ah[mi], Bgh + nj * 2);
                    mma16816(accg[mi][nj], Ah[mi], Bgl + nj * 2);
                    mma16816(accg[mi][nj], Al[mi], Bgh + nj * 2);
                    mma16816(accu[mi][nj], Ah[mi], Buh + nj * 2);
                    mma16816(accu[mi][nj], Ah[mi], Bul + nj * 2);
                    mma16816(accu[mi][nj], Al[mi], Buh + nj * 2);
                }
            }
        }
        __syncthreads();
    }

    // ---- epilogue: silu(g)*u*w -> P
#pragma unroll
    for (int mi = 0; mi < 2; mi++) {
#pragma unroll
        for (int half = 0; half < 2; half++) {
            int mrow = wm * 32 + mi * 16 + (lane >> 2) + half * 8;
            int slot = row0 + mrow;
            if (slot < rows) {
                float wgt = GATHER ? s_wt[mrow] : 1.f;
#pragma unroll
                for (int nj = 0; nj < 2; nj++) {
                    float g0 = accg[mi][nj][half * 2],     u0 = accu[mi][nj][half * 2];
                    float g1 = accg[mi][nj][half * 2 + 1], u1 = accu[mi][nj][half * 2 + 1];
                    float2 o;
                    o.x = (g0 / (1.f + __expf(-g0))) * u0 * wgt;
                    o.y = (g1 / (1.f + __expf(-g1))) * u1 * wgt;
                    int n = col0 + wn * 16 + nj * 8 + (lane & 3) * 2;
                    *(float2*)(P + (size_t)slot * N + n) = o;
                }
            }
        }
    }
}

// ===== down: out (+)= P @ Wd — CTA tile M=128 x N=64, split-bf16 mma.sync =====
template <bool GATHER>
__global__ void __launch_bounds__(256, 2)
down_mma(const float* __restrict__ Wd_g, float* __restrict__ out, int Kd, int T) {
    const int e    = GATHER ? blockIdx.z : 0;
    const int rows = GATHER ? g_cnt[e] : T;
    const int row0 = blockIdx.y * 128;
    if (row0 >= rows) return;
    const int col0 = blockIdx.x * 64;
    const float* Wd = Wd_g + (size_t)e * Kd * H_;
    const float* P  = GATHER ? (g_Pr + (size_t)e * TMAX * Kd) : g_Ps;

    extern __shared__ char smem[];
    uint32_t sb = smem_u32(smem);
    const int tid = threadIdx.x, wid = tid >> 5, lane = tid & 31;
    int* s_tok  = (int*)(smem + SM_TOK);
    int* s_slot = (int*)(smem + SM_WT);

    if (tid < 128) {
        int slot = row0 + tid;
        int cs = slot < rows ? slot : rows - 1;
        s_slot[tid] = cs;
        s_tok[tid]  = GATHER ? g_tok[e * TMAX + cs] : cs;
    }
    __syncthreads();

    const int am = tid >> 1, ah = tid & 1;
    const size_t aoff = (size_t)s_slot[am] * Kd + ah * 32;
    const uint32_t abase = am * 128 + ah * 64;
    const int brow = tid >> 4, bn0 = (tid & 15) * 4;   // 64 n per row, 16 rows/pass

    const int wm = wid & 3, wn = wid >> 2;
    const int a_r  = wm * 32 + (lane & 15);
    const uint32_t xorA = (a_r & 7) << 4;
    const uint32_t a_hi16 = (lane >> 4) * 16;
    const int b_r  = lane & 15;
    const uint32_t xorB = (b_r & 7) << 4;
    const uint32_t nb0 = wn * 64 + a_hi16;             // n-half(32) base bytes

    float acc[2][4][4] = {};

    const int NCH = Kd / 64;
    for (int ch = 0; ch < NCH; ch++) {
        const int k0g = ch * 64;
        {
            const float* ap = P + aoff + k0g;
#pragma unroll
            for (int i = 0; i < 8; i++) {
                float4 v = *(const float4*)(ap + i * 4);
                uint32_t h0, l0, h1, l1;
                splitpair(v.x, v.y, h0, l0);
                splitpair(v.z, v.w, h1, l1);
                uint32_t sw = sw128(abase + i * 8);
                sts64(sb + SM_A_H + sw, h0, h1);
                sts64(sb + SM_A_L + sw, l0, l1);
            }
        }
        {
#pragma unroll
            for (int p = 0; p < 4; p++) {
                int r = brow + p * 16;
                const float* pw = Wd + (size_t)(k0g + r) * H_ + col0 + bn0;
                float4 v = *(const float4*)pw;
                uint32_t h0, l0, h1, l1;
                splitpair(v.x, v.y, h0, l0);
                splitpair(v.z, v.w, h1, l1);
                uint32_t sw = sw128(r * 128 + bn0 * 2);
                sts64(sb + SM_B_H + sw, h0, h1);
                sts64(sb + SM_B_L + sw, l0, l1);
            }
        }
        __syncthreads();

#pragma unroll
        for (int ks = 0; ks < 4; ks++) {
            const uint32_t kb = ks * 32;
            uint32_t Ah[2][4], Al[2][4];
#pragma unroll
            for (int mi = 0; mi < 2; mi++) {
                uint32_t ra = (uint32_t)(a_r + mi * 16) * 128 + ((kb + a_hi16) ^ xorA);
                ldsm4(sb + SM_A_H + ra, Ah[mi]);
                ldsm4(sb + SM_A_L + ra, Al[mi]);
            }
            uint32_t rb = (uint32_t)(ks * 16 + b_r) * 128;
            uint32_t Bh[2][4], Bl[2][4];
#pragma unroll
            for (int nj2 = 0; nj2 < 2; nj2++) {
                uint32_t ba = rb + ((nb0 + nj2 * 32) ^ xorB);
                ldsm4t(sb + SM_B_H + ba, Bh[nj2]);
                ldsm4t(sb + SM_B_L + ba, Bl[nj2]);
            }
#pragma unroll
            for (int mi = 0; mi < 2; mi++) {
#pragma unroll
                for (int nj = 0; nj < 4; nj++) {
                    mma16816(acc[mi][nj], Ah[mi], Bh[nj >> 1] + (nj & 1) * 2);
                    mma16816(acc[mi][nj], Ah[mi], Bl[nj >> 1] + (nj & 1) * 2);
                    mma16816(acc[mi][nj], Al[mi], Bh[nj >> 1] + (nj & 1) * 2);
                }
            }
        }
        __syncthreads();
    }

#pragma unroll
    for (int mi = 0; mi < 2; mi++) {
#pragma unroll
        for (int half = 0; half < 2; half++) {
            int mrow = wm * 32 + mi * 16 + (lane >> 2) + half * 8;
            int slot = row0 + mrow;
            if (slot < rows) {
                float* orow = out + (size_t)s_tok[mrow] * H_;
#pragma unroll
                for (int nj = 0; nj < 4; nj++) {
                    int n = col0 + wn * 32 + nj * 8 + (lane & 3) * 2;
                    float v0 = acc[mi][nj][half * 2], v1 = acc[mi][nj][half * 2 + 1];
                    if (GATHER) {
                        atomicAdd(&orow[n], v0);
                        atomicAdd(&orow[n + 1], v1);
                    } else {
                        *(float2*)(orow + n) = make_float2(v0, v1);
                    }
                }
            }
        }
    }
}

extern "C" void kernel_launch(void* const* d_in, const int* in_sizes, int n_in,
                              void* d_out, int out_size) {
    const float* X   = (const float*)d_in[0];
    const float* gw  = (const float*)d_in[1];
    const float* Wg  = (const float*)d_in[2];
    const float* Wu  = (const float*)d_in[3];
    const float* Wd  = (const float*)d_in[4];
    const float* sWg = (const float*)d_in[5];
    const float* sWu = (const float*)d_in[6];
    const float* sWd = (const float*)d_in[7];
    float* out = (float*)d_out;

    int T = in_sizes[0] / H_;   // 2048

    static bool attr_done = false;
    if (!attr_done) {
        cudaFuncSetAttribute(up_mma<false>,   cudaFuncAttributeMaxDynamicSharedMemorySize, SMEM_BYTES);
        cudaFuncSetAttribute(up_mma<true>,    cudaFuncAttributeMaxDynamicSharedMemorySize, SMEM_BYTES);
        cudaFuncSetAttribute(down_mma<false>, cudaFuncAttributeMaxDynamicSharedMemorySize, SMEM_BYTES);
        cudaFuncSetAttribute(down_mma<true>,  cudaFuncAttributeMaxDynamicSharedMemorySize, SMEM_BYTES);
        attr_done = true;
    }

    zero_cnt_kernel<<<1, 32>>>();
    router_kernel<<<(T + 7) / 8, 256>>>(X, gw, T);

    int ry = (T + 127) / 128;
    // shared up -> g_Ps
    up_mma<false><<<dim3(IS_ / 32, ry), 256, SMEM_BYTES>>>(X, sWg, sWu, IS_, T);
    // routed up -> g_Pr (routing weight folded in)
    up_mma<true><<<dim3(IM_ / 32, ry, E_), 256, SMEM_BYTES>>>(X, Wg, Wu, IM_, T);
    // shared down: plain store (initializes out)
    down_mma<false><<<dim3(H_ / 64, ry), 256, SMEM_BYTES>>>(sWd, out, IS_, T);
    // routed down: scatter atomicAdd
    down_mma<true><<<dim3(H_ / 64, ry, E_), 256, SMEM_BYTES>>>(Wd, out, IM_, T);
}

// round 11
// speedup vs baseline: 1.4052x; 1.3617x over previous
#include <cuda_runtime.h>
#include <cuda_bf16.h>
#include <cstdint>
#include <math.h>

static constexpr int H_   = 2048;
static constexpr int IM_  = 1024;
static constexpr int IS_  = 2048;
static constexpr int E_   = 16;
static constexpr int K_   = 8;
static constexpr int TMAX = 2048;
static constexpr float SCALE_ = 2.5f;

typedef __nv_bfloat16 bf16;

// ---------------- scratch (device globals) ----------------
__device__ int   g_cnt[E_];
__device__ int   g_tok[E_ * TMAX];
__device__ float g_wt [E_ * TMAX];
// pre-split hi/lo bf16 planes
__device__ bf16 g_Xh[(size_t)TMAX * H_],      g_Xl[(size_t)TMAX * H_];
__device__ bf16 g_sWgh[(size_t)H_ * IS_],     g_sWgl[(size_t)H_ * IS_];
__device__ bf16 g_sWuh[(size_t)H_ * IS_],     g_sWul[(size_t)H_ * IS_];
__device__ bf16 g_sWdh[(size_t)IS_ * H_],     g_sWdl[(size_t)IS_ * H_];
__device__ bf16 g_Wgh[(size_t)E_ * H_ * IM_], g_Wgl[(size_t)E_ * H_ * IM_];
__device__ bf16 g_Wuh[(size_t)E_ * H_ * IM_], g_Wul[(size_t)E_ * H_ * IM_];
__device__ bf16 g_Wdh[(size_t)E_ * IM_ * H_], g_Wdl[(size_t)E_ * IM_ * H_];
__device__ bf16 g_Psh[(size_t)TMAX * IS_],    g_Psl[(size_t)TMAX * IS_];
__device__ bf16 g_Prh[(size_t)E_ * TMAX * IM_], g_Prl[(size_t)E_ * TMAX * IM_];

// ---------------- helpers ----------------
__device__ __forceinline__ uint32_t smem_u32(const void* p) {
    uint32_t a;
    asm("{ .reg .u64 t; cvta.to.shared.u64 t, %1; cvt.u32.u64 %0, t; }" : "=r"(a) : "l"(p));
    return a;
}
__device__ __forceinline__ uint32_t sw128(uint32_t o) { return o ^ ((o >> 3) & 0x70); }

__device__ __forceinline__ void splitpair(float x0, float x1, uint32_t& hi, uint32_t& lo) {
    asm("cvt.rn.bf16x2.f32 %0, %1, %2;" : "=r"(hi) : "f"(x1), "f"(x0));
    float h0 = __uint_as_float(hi << 16);
    float h1 = __uint_as_float(hi & 0xffff0000u);
    float l0 = x0 - h0, l1 = x1 - h1;
    asm("cvt.rn.bf16x2.f32 %0, %1, %2;" : "=r"(lo) : "f"(l1), "f"(l0));
}
__device__ __forceinline__ void cp16(uint32_t dst, const void* src) {
    asm volatile("cp.async.ca.shared.global [%0], [%1], 16;" :: "r"(dst), "l"(src));
}
#define CP_COMMIT() asm volatile("cp.async.commit_group;" ::: "memory")
#define CP_WAIT(n)  asm volatile("cp.async.wait_group %0;" :: "n"(n) : "memory")

__device__ __forceinline__ void ldsm4(uint32_t addr, uint32_t* r) {
    asm volatile("ldmatrix.sync.aligned.m8n8.x4.shared.b16 {%0,%1,%2,%3}, [%4];"
        : "=r"(r[0]), "=r"(r[1]), "=r"(r[2]), "=r"(r[3]) : "r"(addr));
}
__device__ __forceinline__ void ldsm4t(uint32_t addr, uint32_t* r) {
    asm volatile("ldmatrix.sync.aligned.m8n8.x4.trans.shared.b16 {%0,%1,%2,%3}, [%4];"
        : "=r"(r[0]), "=r"(r[1]), "=r"(r[2]), "=r"(r[3]) : "r"(addr));
}
__device__ __forceinline__ void mma16816(float* d, const uint32_t* a, const uint32_t* b) {
    asm volatile("mma.sync.aligned.m16n8k16.row.col.f32.bf16.bf16.f32 "
        "{%0,%1,%2,%3}, {%4,%5,%6,%7}, {%8,%9}, {%0,%1,%2,%3};"
        : "+f"(d[0]), "+f"(d[1]), "+f"(d[2]), "+f"(d[3])
        : "r"(a[0]), "r"(a[1]), "r"(a[2]), "r"(a[3]), "r"(b[0]), "r"(b[1]));
}

// smem layout: [tok 512][wt 512][stage0 32KB][stage1 32KB]
static constexpr int SM_TOK   = 0;
static constexpr int SM_WT    = 512;
static constexpr int SM_TILES = 1024;
static constexpr int STAGE_BYTES = 32768;   // A 16KB + B 16KB
static constexpr int SM_B_OFF = 16384;      // B tiles start within stage
static constexpr int SMEM_BYTES = SM_TILES + 2 * STAGE_BYTES;  // 66560

// ---------------- small kernels ----------------
__global__ void zero_cnt_kernel() { if (threadIdx.x < E_) g_cnt[threadIdx.x] = 0; }

__global__ void convert_split(const float* __restrict__ src, bf16* __restrict__ h,
                              bf16* __restrict__ l, size_t n4) {
    size_t i = (size_t)blockIdx.x * blockDim.x + threadIdx.x;
    size_t stride = (size_t)gridDim.x * blockDim.x;
    const float4* s4 = (const float4*)src;
    uint32_t* h2 = (uint32_t*)h;
    uint32_t* l2 = (uint32_t*)l;
    for (; i < n4; i += stride) {
        float4 v = s4[i];
        uint32_t h0, l0, h1, l1;
        splitpair(v.x, v.y, h0, l0);
        splitpair(v.z, v.w, h1, l1);
        h2[i * 2] = h0; h2[i * 2 + 1] = h1;
        l2[i * 2] = l0; l2[i * 2 + 1] = l1;
    }
}

__global__ void router_kernel(const float* __restrict__ X, const float* __restrict__ gw, int T) {
    int gtid = blockIdx.x * blockDim.x + threadIdx.x;
    int t = gtid >> 5, lane = gtid & 31;
    if (t >= T) return;
    const float* h = X + (size_t)t * H_;
    float acc[E_];
#pragma unroll
    for (int e = 0; e < E_; e++) acc[e] = 0.f;
    for (int i = lane; i < H_; i += 32) {
        float hv = h[i];
#pragma unroll
        for (int e = 0; e < E_; e++) acc[e] += hv * gw[e * H_ + i];
    }
#pragma unroll
    for (int e = 0; e < E_; e++)
#pragma unroll
        for (int o = 16; o > 0; o >>= 1) acc[e] += __shfl_xor_sync(0xffffffffu, acc[e], o);
    if (lane == 0) {
        float w[E_];
#pragma unroll
        for (int e = 0; e < E_; e++) w[e] = 1.f / (1.f + expf(-acc[e]));
        bool used[E_] = {};
        int sel[K_]; float sv[K_]; float sum = 0.f;
        for (int k = 0; k < K_; k++) {
            int best = 0; float bv = -1.f;
            for (int e = 0; e < E_; e++)
                if (!used[e] && w[e] > bv) { bv = w[e]; best = e; }
            used[best] = true; sel[k] = best; sv[k] = bv; sum += bv;
        }
        float norm = SCALE_ / (sum + 1e-6f);
        for (int k = 0; k < K_; k++) {
            int e = sel[k];
            int p = atomicAdd(&g_cnt[e], 1);
            g_tok[e * TMAX + p] = t;
            g_wt [e * TMAX + p] = sv[k] * norm;
        }
    }
}

// ===== up: P = silu(A@Wg)*(A@Wu)[*w] — CTA 128m x 64n(G)+64n(U), K-chunk 32, cp.async 2-stage =====
template <bool GATHER>
__global__ void __launch_bounds__(256, 2)
up_mma(const bf16* __restrict__ Xh, const bf16* __restrict__ Xl,
       const bf16* __restrict__ Wgh_g, const bf16* __restrict__ Wgl_g,
       const bf16* __restrict__ Wuh_g, const bf16* __restrict__ Wul_g,
       bf16* __restrict__ Ph_g, bf16* __restrict__ Pl_g, int N, int T) {
    const int e    = GATHER ? blockIdx.z : 0;
    const int rows = GATHER ? g_cnt[e] : T;
    const int row0 = blockIdx.y * 128;
    if (row0 >= rows) return;
    const int col0 = blockIdx.x * 64;
    const size_t woff = (size_t)e * H_ * N;
    const bf16* Wgh = Wgh_g + woff; const bf16* Wgl = Wgl_g + woff;
    const bf16* Wuh = Wuh_g + woff; const bf16* Wul = Wul_g + woff;
    bf16* Ph = GATHER ? (Ph_g + (size_t)e * TMAX * N) : Ph_g;
    bf16* Pl = GATHER ? (Pl_g + (size_t)e * TMAX * N) : Pl_g;

    extern __shared__ char smem[];
    uint32_t sb = smem_u32(smem);
    const int tid = threadIdx.x, wid = tid >> 5, lane = tid & 31;
    int*   s_tok = (int*)(smem + SM_TOK);
    float* s_wt  = (float*)(smem + SM_WT);

    if (tid < 128) {
        int slot = row0 + tid;
        int cs = slot < rows ? slot : rows - 1;
        if (GATHER) { s_tok[tid] = g_tok[e * TMAX + cs]; s_wt[tid] = g_wt[e * TMAX + cs]; }
        else        { s_tok[tid] = cs; }
    }
    __syncthreads();

    // loader assignments
    const int a_row = tid >> 1, a_half = tid & 1;
    const bf16* a_src = (a_half ? Xl : Xh) + (size_t)s_tok[a_row] * H_;
    const uint32_t a_dst_row = a_row * 128 + a_half * 64;
    const int b_tile = tid >> 6;                 // 0=GH 1=GL 2=UH 3=UL
    const int b_r    = (tid >> 1) & 31;
    const int b_part = tid & 1;
    const bf16* b_src = (b_tile == 0 ? Wgh : b_tile == 1 ? Wgl : b_tile == 2 ? Wuh : Wul)
                        + (size_t)b_r * N + col0 + b_part * 32;
    const uint32_t b_dst_row = b_tile * 4096 + b_r * 128 + b_part * 64;

    // fragment addressing
    const int wm = wid & 3, wn = wid >> 2;
    const int a_r = wm * 32 + (lane & 15);
    const uint32_t xorA = (a_r & 7) << 4;
    const uint32_t hi16 = (lane >> 4) * 16;
    const int bfr = lane & 15;
    const uint32_t xorB = (bfr & 7) << 4;

    float accg[2][4][4] = {}, accu[2][4][4] = {};

    const int NCH = H_ / 32;
    // prologue: stage 0
    {
        uint32_t st = sb + SM_TILES;
#pragma unroll
        for (int i = 0; i < 4; i++) {
            cp16(st + sw128(a_dst_row + i * 16), a_src + i * 8);
            cp16(st + SM_B_OFF + sw128(b_dst_row + i * 16), b_src + i * 8);
        }
        CP_COMMIT();
    }

    for (int ch = 0; ch < NCH; ch++) {
        if (ch + 1 < NCH) {
            const int k0 = (ch + 1) * 32;
            uint32_t st = sb + SM_TILES + ((ch + 1) & 1) * STAGE_BYTES;
            const bf16* as = a_src + k0;
            const bf16* bs = b_src + (size_t)k0 * N;
#pragma unroll
            for (int i = 0; i < 4; i++) {
                cp16(st + sw128(a_dst_row + i * 16), as + i * 8);
                cp16(st + SM_B_OFF + sw128(b_dst_row + i * 16), bs + i * 8);
            }
            CP_COMMIT();
            CP_WAIT(1);
        } else {
            CP_WAIT(0);
        }
        __syncthreads();

        uint32_t st  = sb + SM_TILES + (ch & 1) * STAGE_BYTES;
        uint32_t bGH = st + SM_B_OFF,      bGL = bGH + 4096;
        uint32_t bUH = bGL + 4096,         bUL = bUH + 4096;
#pragma unroll
        for (int ks = 0; ks < 2; ks++) {
            const uint32_t kb = ks * 32;
            uint32_t Ah[2][4], Al[2][4];
#pragma unroll
            for (int mi = 0; mi < 2; mi++) {
                uint32_t rowb = (uint32_t)(a_r + mi * 16) * 128;
                ldsm4(st + rowb + ((kb + hi16) ^ xorA), Ah[mi]);
                ldsm4(st + rowb + ((64 + kb + hi16) ^ xorA), Al[mi]);
            }
            const uint32_t rb = (uint32_t)(ks * 16 + bfr) * 128;
#pragma unroll
            for (int q = 0; q < 2; q++) {
                uint32_t colq = (wn * 64 + q * 32 + hi16) ^ xorB;
                uint32_t bh[4], bl[4];
                ldsm4t(bGH + rb + colq, bh);
                ldsm4t(bGL + rb + colq, bl);
#pragma unroll
                for (int mi = 0; mi < 2; mi++)
#pragma unroll
                    for (int sub = 0; sub < 2; sub++) {
                        float* d = accg[mi][q * 2 + sub];
                        mma16816(d, Ah[mi], bh + sub * 2);
                        mma16816(d, Ah[mi], bl + sub * 2);
                        mma16816(d, Al[mi], bh + sub * 2);
                    }
                ldsm4t(bUH + rb + colq, bh);
                ldsm4t(bUL + rb + colq, bl);
#pragma unroll
                for (int mi = 0; mi < 2; mi++)
#pragma unroll
                    for (int sub = 0; sub < 2; sub++) {
                        float* d = accu[mi][q * 2 + sub];
                        mma16816(d, Ah[mi], bh + sub * 2);
                        mma16816(d, Ah[mi], bl + sub * 2);
                        mma16816(d, Al[mi], bh + sub * 2);
                    }
            }
        }
        __syncthreads();
    }

    // epilogue: silu(g)*u*w -> P hi/lo planes
#pragma unroll
    for (int mi = 0; mi < 2; mi++)
#pragma unroll
        for (int half = 0; half < 2; half++) {
            int mrow = wm * 32 + mi * 16 + (lane >> 2) + half * 8;
            int slot = row0 + mrow;
            if (slot < rows) {
                float wgt = GATHER ? s_wt[mrow] : 1.f;
#pragma unroll
                for (int nj = 0; nj < 4; nj++) {
                    float g0 = accg[mi][nj][half * 2],     u0 = accu[mi][nj][half * 2];
                    float g1 = accg[mi][nj][half * 2 + 1], u1 = accu[mi][nj][half * 2 + 1];
                    float v0 = (g0 / (1.f + __expf(-g0))) * u0 * wgt;
                    float v1 = (g1 / (1.f + __expf(-g1))) * u1 * wgt;
                    uint32_t hi, lo;
                    splitpair(v0, v1, hi, lo);
                    int n = col0 + wn * 32 + nj * 8 + (lane & 3) * 2;
                    size_t off = (size_t)slot * N + n;
                    *(uint32_t*)(Ph + off) = hi;
                    *(uint32_t*)(Pl + off) = lo;
                }
            }
        }
}

// ===== down: out (+)= P @ Wd — CTA 128m x 128n, K-chunk 32, cp.async 2-stage =====
template <bool GATHER>
__global__ void __launch_bounds__(256, 2)
down_mma(const bf16* __restrict__ Ph_g, const bf16* __restrict__ Pl_g,
         const bf16* __restrict__ Wdh_g, const bf16* __restrict__ Wdl_g,
         float* __restrict__ out, int Kd, int T) {
    const int e    = GATHER ? blockIdx.z : 0;
    const int rows = GATHER ? g_cnt[e] : T;
    const int row0 = blockIdx.y * 128;
    if (row0 >= rows) return;
    const int col0 = blockIdx.x * 128;
    const size_t woff = (size_t)e * Kd * H_;
    const bf16* Wdh = Wdh_g + woff;
    const bf16* Wdl = Wdl_g + woff;
    const bf16* Ph = GATHER ? (Ph_g + (size_t)e * TMAX * Kd) : Ph_g;
    const bf16* Pl = GATHER ? (Pl_g + (size_t)e * TMAX * Kd) : Pl_g;

    extern __shared__ char smem[];
    uint32_t sb = smem_u32(smem);
    const int tid = threadIdx.x, wid = tid >> 5, lane = tid & 31;
    int* s_tok  = (int*)(smem + SM_TOK);
    int* s_slot = (int*)(smem + SM_WT);

    if (tid < 128) {
        int slot = row0 + tid;
        int cs = slot < rows ? slot : rows - 1;
        s_slot[tid] = cs;
        s_tok[tid]  = GATHER ? g_tok[e * TMAX + cs] : cs;
    }
    __syncthreads();

    const int a_row = tid >> 1, a_half = tid & 1;
    const bf16* a_src = (a_half ? Pl : Ph) + (size_t)s_slot[a_row] * Kd;
    const uint32_t a_dst_row = a_row * 128 + a_half * 64;
    const int b_tile = tid >> 6;                 // (half<<1)|plane: 0=n0H 1=n0L 2=n1H 3=n1L
    const int b_half = b_tile >> 1, b_plane = b_tile & 1;
    const int b_r    = (tid >> 1) & 31;
    const int b_part = tid & 1;
    const bf16* b_src = (b_plane ? Wdl : Wdh)
                        + (size_t)b_r * H_ + col0 + b_half * 64 + b_part * 32;
    const uint32_t b_dst_row = b_tile * 4096 + b_r * 128 + b_part * 64;

    const int wm = wid & 3, wn = wid >> 2;
    const int a_r = wm * 32 + (lane & 15);
    const uint32_t xorA = (a_r & 7) << 4;
    const uint32_t hi16 = (lane >> 4) * 16;
    const int bfr = lane & 15;
    const uint32_t xorB = (bfr & 7) << 4;

    float acc[2][8][4] = {};

    const int NCH = Kd / 32;
    {
        uint32_t st = sb + SM_TILES;
#pragma unroll
        for (int i = 0; i < 4; i++) {
            cp16(st + sw128(a_dst_row + i * 16), a_src + i * 8);
            cp16(st + SM_B_OFF + sw128(b_dst_row + i * 16), b_src + i * 8);
        }
        CP_COMMIT();
    }

    for (int ch = 0; ch < NCH; ch++) {
        if (ch + 1 < NCH) {
            const int k0 = (ch + 1) * 32;
            uint32_t st = sb + SM_TILES + ((ch + 1) & 1) * STAGE_BYTES;
            const bf16* as = a_src + k0;
            const bf16* bs = b_src + (size_t)k0 * H_;
#pragma unroll
            for (int i = 0; i < 4; i++) {
                cp16(st + sw128(a_dst_row + i * 16), as + i * 8);
                cp16(st + SM_B_OFF + sw128(b_dst_row + i * 16), bs + i * 8);
            }
            CP_COMMIT();
            CP_WAIT(1);
        } else {
            CP_WAIT(0);
        }
        __syncthreads();

        uint32_t st = sb + SM_TILES + (ch & 1) * STAGE_BYTES;
        // warp wn reads its n-half tile pair
        uint32_t bH = st + SM_B_OFF + wn * 8192;
        uint32_t bL = bH + 4096;
#pragma unroll
        for (int ks = 0; ks < 2; ks++) {
            const uint32_t kb = ks * 32;
            uint32_t Ah[2][4], Al[2][4];
#pragma unroll
            for (int mi = 0; mi < 2; mi++) {
                uint32_t rowb = (uint32_t)(a_r + mi * 16) * 128;
                ldsm4(st + rowb + ((kb + hi16) ^ xorA), Ah[mi]);
                ldsm4(st + rowb + ((64 + kb + hi16) ^ xorA), Al[mi]);
            }
            const uint32_t rb = (uint32_t)(ks * 16 + bfr) * 128;
#pragma unroll
            for (int q = 0; q < 4; q++) {
                uint32_t colq = (q * 32 + hi16) ^ xorB;
                uint32_t bh[4], bl[4];
                ldsm4t(bH + rb + colq, bh);
                ldsm4t(bL + rb + colq, bl);
#pragma unroll
                for (int mi = 0; mi < 2; mi++)
#pragma unroll
                    for (int sub = 0; sub < 2; sub++) {
                        float* d = acc[mi][q * 2 + sub];
                        mma16816(d, Ah[mi], bh + sub * 2);
                        mma16816(d, Ah[mi], bl + sub * 2);
                        mma16816(d, Al[mi], bh + sub * 2);
                    }
            }
        }
        __syncthreads();
    }

#pragma unroll
    for (int mi = 0; mi < 2; mi++)
#pragma unroll
        for (int half = 0; half < 2; half++) {
            int mrow = wm * 32 + mi * 16 + (lane >> 2) + half * 8;
            int slot = row0 + mrow;
            if (slot < rows) {
                float* orow = out + (size_t)s_tok[mrow] * H_;
#pragma unroll
                for (int nj = 0; nj < 8; nj++) {
                    int n = col0 + wn * 64 + nj * 8 + (lane & 3) * 2;
                    float v0 = acc[mi][nj][half * 2], v1 = acc[mi][nj][half * 2 + 1];
                    if (GATHER) {
                        atomicAdd(&orow[n], v0);
                        atomicAdd(&orow[n + 1], v1);
                    } else {
                        *(float2*)(orow + n) = make_float2(v0, v1);
                    }
                }
            }
        }
}

// ---------------- launch ----------------
extern "C" void kernel_launch(void* const* d_in, const int* in_sizes, int n_in,
                              void* d_out, int out_size) {
    const float* X   = (const float*)d_in[0];
    const float* gw  = (const float*)d_in[1];
    const float* Wg  = (const float*)d_in[2];
    const float* Wu  = (const float*)d_in[3];
    const float* Wd  = (const float*)d_in[4];
    const float* sWg = (const float*)d_in[5];
    const float* sWu = (const float*)d_in[6];
    const float* sWd = (const float*)d_in[7];
    float* out = (float*)d_out;

    int T = in_sizes[0] / H_;   // 2048

    static bool attr_done = false;
    if (!attr_done) {
        cudaFuncSetAttribute(up_mma<false>,   cudaFuncAttributeMaxDynamicSharedMemorySize, SMEM_BYTES);
        cudaFuncSetAttribute(up_mma<true>,    cudaFuncAttributeMaxDynamicSharedMemorySize, SMEM_BYTES);
        cudaFuncSetAttribute(down_mma<false>, cudaFuncAttributeMaxDynamicSharedMemorySize, SMEM_BYTES);
        cudaFuncSetAttribute(down_mma<true>,  cudaFuncAttributeMaxDynamicSharedMemorySize, SMEM_BYTES);
        attr_done = true;
    }

    // resolve device-global addresses (host side, graph-capturable: done per call, cheap)
    bf16 *Xh, *Xl, *sWgh, *sWgl, *sWuh, *sWul, *sWdh, *sWdl;
    bf16 *Wgh, *Wgl, *Wuh, *Wul, *Wdh, *Wdl, *Psh, *Psl, *Prh, *Prl;
    cudaGetSymbolAddress((void**)&Xh,  g_Xh);   cudaGetSymbolAddress((void**)&Xl,  g_Xl);
    cudaGetSymbolAddress((void**)&sWgh, g_sWgh); cudaGetSymbolAddress((void**)&sWgl, g_sWgl);
    cudaGetSymbolAddress((void**)&sWuh, g_sWuh); cudaGetSymbolAddress((void**)&sWul, g_sWul);
    cudaGetSymbolAddress((void**)&sWdh, g_sWdh); cudaGetSymbolAddress((void**)&sWdl, g_sWdl);
    cudaGetSymbolAddress((void**)&Wgh, g_Wgh);  cudaGetSymbolAddress((void**)&Wgl, g_Wgl);
    cudaGetSymbolAddress((void**)&Wuh, g_Wuh);  cudaGetSymbolAddress((void**)&Wul, g_Wul);
    cudaGetSymbolAddress((void**)&Wdh, g_Wdh);  cudaGetSymbolAddress((void**)&Wdl, g_Wdl);
    cudaGetSymbolAddress((void**)&Psh, g_Psh);  cudaGetSymbolAddress((void**)&Psl, g_Psl);
    cudaGetSymbolAddress((void**)&Prh, g_Prh);  cudaGetSymbolAddress((void**)&Prl, g_Prl);

    zero_cnt_kernel<<<1, 32>>>();
    router_kernel<<<(T + 7) / 8, 256>>>(X, gw, T);

    // pre-split conversions (streaming)
    const int CB = 1184, CT = 256;
    convert_split<<<CB, CT>>>(X,   Xh,   Xl,   (size_t)T * H_ / 4);
    convert_split<<<CB, CT>>>(sWg, sWgh, sWgl, (size_t)H_ * IS_ / 4);
    convert_split<<<CB, CT>>>(sWu, sWuh, sWul, (size_t)H_ * IS_ / 4);
    convert_split<<<CB, CT>>>(sWd, sWdh, sWdl, (size_t)IS_ * H_ / 4);
    convert_split<<<CB, CT>>>(Wg,  Wgh,  Wgl,  (size_t)E_ * H_ * IM_ / 4);
    convert_split<<<CB, CT>>>(Wu,  Wuh,  Wul,  (size_t)E_ * H_ * IM_ / 4);
    convert_split<<<CB, CT>>>(Wd,  Wdh,  Wdl,  (size_t)E_ * IM_ * H_ / 4);

    int ry = (T + 127) / 128;
    // shared up -> Ps planes
    up_mma<false><<<dim3(IS_ / 64, ry), 256, SMEM_BYTES>>>(
        Xh, Xl, sWgh, sWgl, sWuh, sWul, Psh, Psl, IS_, T);
    // routed up -> Pr planes (routing weight folded in)
    up_mma<true><<<dim3(IM_ / 64, ry, E_), 256, SMEM_BYTES>>>(
        Xh, Xl, Wgh, Wgl, Wuh, Wul, Prh, Prl, IM_, T);
    // shared down: plain store (initializes out)
    down_mma<false><<<dim3(H_ / 128, ry), 256, SMEM_BYTES>>>(
        Psh, Psl, sWdh, sWdl, out, IS_, T);
    // routed down: scatter atomicAdd
    down_mma<true><<<dim3(H_ / 128, ry, E_), 256, SMEM_BYTES>>>(
        Prh, Prl, Wdh, Wdl, out, IM_, T);
}

// round 15
// speedup vs baseline: 1.9240x; 1.3692x over previous
#include <cuda_runtime.h>
#include <cuda_bf16.h>
#include <cstdint>
#include <math.h>

static constexpr int H_   = 2048;
static constexpr int IM_  = 1024;
static constexpr int IS_  = 2048;
static constexpr int E_   = 16;
static constexpr int K_   = 8;
static constexpr int TMAX = 2048;
static constexpr float SCALE_ = 2.5f;

typedef __nv_bfloat16 bf16;

// ---------------- scratch (device globals) ----------------
__device__ int   g_cnt[E_];
__device__ int   g_tok[E_ * TMAX];
__device__ float g_wt [E_ * TMAX];
__device__ bf16 g_Xh[(size_t)TMAX * H_],      g_Xl[(size_t)TMAX * H_];
__device__ bf16 g_sWgh[(size_t)H_ * IS_],     g_sWgl[(size_t)H_ * IS_];
__device__ bf16 g_sWuh[(size_t)H_ * IS_],     g_sWul[(size_t)H_ * IS_];
__device__ bf16 g_sWdh[(size_t)IS_ * H_],     g_sWdl[(size_t)IS_ * H_];
__device__ bf16 g_Wgh[(size_t)E_ * H_ * IM_], g_Wgl[(size_t)E_ * H_ * IM_];
__device__ bf16 g_Wuh[(size_t)E_ * H_ * IM_], g_Wul[(size_t)E_ * H_ * IM_];
__device__ bf16 g_Wdh[(size_t)E_ * IM_ * H_], g_Wdl[(size_t)E_ * IM_ * H_];
__device__ bf16 g_Psh[(size_t)TMAX * IS_],    g_Psl[(size_t)TMAX * IS_];
__device__ bf16 g_Prh[(size_t)E_ * TMAX * IM_], g_Prl[(size_t)E_ * TMAX * IM_];

// ---------------- helpers ----------------
__device__ __forceinline__ uint32_t smem_u32(const void* p) {
    uint32_t a;
    asm("{ .reg .u64 t; cvta.to.shared.u64 t, %1; cvt.u32.u64 %0, t; }" : "=r"(a) : "l"(p));
    return a;
}
__device__ __forceinline__ uint32_t sw128(uint32_t o) { return o ^ ((o >> 3) & 0x70); }

__device__ __forceinline__ void splitpair(float x0, float x1, uint32_t& hi, uint32_t& lo) {
    asm("cvt.rn.bf16x2.f32 %0, %1, %2;" : "=r"(hi) : "f"(x1), "f"(x0));
    float h0 = __uint_as_float(hi << 16);
    float h1 = __uint_as_float(hi & 0xffff0000u);
    float l0 = x0 - h0, l1 = x1 - h1;
    asm("cvt.rn.bf16x2.f32 %0, %1, %2;" : "=r"(lo) : "f"(l1), "f"(l0));
}
__device__ __forceinline__ void cp16(uint32_t dst, const void* src) {
    asm volatile("cp.async.ca.shared.global [%0], [%1], 16;" :: "r"(dst), "l"(src));
}
#define CP_COMMIT() asm volatile("cp.async.commit_group;" ::: "memory")
#define CP_WAIT(n)  asm volatile("cp.async.wait_group %0;" :: "n"(n) : "memory")

__device__ __forceinline__ void ldsm4(uint32_t addr, uint32_t* r) {
    asm volatile("ldmatrix.sync.aligned.m8n8.x4.shared.b16 {%0,%1,%2,%3}, [%4];"
        : "=r"(r[0]), "=r"(r[1]), "=r"(r[2]), "=r"(r[3]) : "r"(addr));
}
__device__ __forceinline__ void ldsm4t(uint32_t addr, uint32_t* r) {
    asm volatile("ldmatrix.sync.aligned.m8n8.x4.trans.shared.b16 {%0,%1,%2,%3}, [%4];"
        : "=r"(r[0]), "=r"(r[1]), "=r"(r[2]), "=r"(r[3]) : "r"(addr));
}
__device__ __forceinline__ void mma16816(float* d, const uint32_t* a, const uint32_t* b) {
    asm volatile("mma.sync.aligned.m16n8k16.row.col.f32.bf16.bf16.f32 "
        "{%0,%1,%2,%3}, {%4,%5,%6,%7}, {%8,%9}, {%0,%1,%2,%3};"
        : "+f"(d[0]), "+f"(d[1]), "+f"(d[2]), "+f"(d[3])
        : "r"(a[0]), "r"(a[1]), "r"(a[2]), "r"(a[3]), "r"(b[0]), "r"(b[1]));
}

// smem layout: [tok 512][wt 512][3 stages x 32KB]
static constexpr int SM_TOK   = 0;
static constexpr int SM_WT    = 512;
static constexpr int SM_TILES = 1024;
static constexpr int STAGE_BYTES = 32768;   // A 16KB + B 16KB
static constexpr int SM_B_OFF = 16384;
static constexpr int N_STAGES = 3;
static constexpr int SMEM_BYTES = SM_TILES + N_STAGES * STAGE_BYTES;  // 99328

// ---------------- small kernels ----------------
__global__ void zero_cnt_kernel() { if (threadIdx.x < E_) g_cnt[threadIdx.x] = 0; }

__global__ void convert_split(const float* __restrict__ src, bf16* __restrict__ h,
                              bf16* __restrict__ l, size_t n4) {
    size_t stride = (size_t)gridDim.x * blockDim.x;
    size_t i = (size_t)blockIdx.x * blockDim.x + threadIdx.x;
    const float4* s4 = (const float4*)src;
    uint32_t* h2 = (uint32_t*)h;
    uint32_t* l2 = (uint32_t*)l;
    for (; i + stride < n4; i += 2 * stride) {
        float4 v0 = __ldcs(&s4[i]);
        float4 v1 = __ldcs(&s4[i + stride]);
        uint32_t a0, b0, a1, b1;
        splitpair(v0.x, v0.y, a0, b0); splitpair(v0.z, v0.w, a1, b1);
        h2[i * 2] = a0; h2[i * 2 + 1] = a1;
        l2[i * 2] = b0; l2[i * 2 + 1] = b1;
        size_t j = i + stride;
        splitpair(v1.x, v1.y, a0, b0); splitpair(v1.z, v1.w, a1, b1);
        h2[j * 2] = a0; h2[j * 2 + 1] = a1;
        l2[j * 2] = b0; l2[j * 2 + 1] = b1;
    }
    if (i < n4) {
        float4 v = __ldcs(&s4[i]);
        uint32_t a0, b0, a1, b1;
        splitpair(v.x, v.y, a0, b0); splitpair(v.z, v.w, a1, b1);
        h2[i * 2] = a0; h2[i * 2 + 1] = a1;
        l2[i * 2] = b0; l2[i * 2 + 1] = b1;
    }
}

__global__ void router_kernel(const float* __restrict__ X, const float* __restrict__ gw, int T) {
    int gtid = blockIdx.x * blockDim.x + threadIdx.x;
    int t = gtid >> 5, lane = gtid & 31;
    if (t >= T) return;
    const float* h = X + (size_t)t * H_;
    float acc[E_];
#pragma unroll
    for (int e = 0; e < E_; e++) acc[e] = 0.f;
    for (int i = lane; i < H_; i += 32) {
        float hv = h[i];
#pragma unroll
        for (int e = 0; e < E_; e++) acc[e] += hv * gw[e * H_ + i];
    }
#pragma unroll
    for (int e = 0; e < E_; e++)
#pragma unroll
        for (int o = 16; o > 0; o >>= 1) acc[e] += __shfl_xor_sync(0xffffffffu, acc[e], o);
    if (lane == 0) {
        float w[E_];
#pragma unroll
        for (int e = 0; e < E_; e++) w[e] = 1.f / (1.f + expf(-acc[e]));
        bool used[E_] = {};
        int sel[K_]; float sv[K_]; float sum = 0.f;
        for (int k = 0; k < K_; k++) {
            int best = 0; float bv = -1.f;
            for (int e = 0; e < E_; e++)
                if (!used[e] && w[e] > bv) { bv = w[e]; best = e; }
            used[best] = true; sel[k] = best; sv[k] = bv; sum += bv;
        }
        float norm = SCALE_ / (sum + 1e-6f);
        for (int k = 0; k < K_; k++) {
            int e = sel[k];
            int p = atomicAdd(&g_cnt[e], 1);
            g_tok[e * TMAX + p] = t;
            g_wt [e * TMAX + p] = sv[k] * norm;
        }
    }
}

// ===== up: P = silu(A@Wg)*(A@Wu)[*w] — CTA 128m x 64n(G+U), k-chunk 32, 3-stage, frag prefetch =====
template <bool GATHER>
__global__ void __launch_bounds__(256, 2)
up_mma(const bf16* __restrict__ Xh, const bf16* __restrict__ Xl,
       const bf16* __restrict__ Wgh_g, const bf16* __restrict__ Wgl_g,
       const bf16* __restrict__ Wuh_g, const bf16* __restrict__ Wul_g,
       bf16* __restrict__ Ph_g, bf16* __restrict__ Pl_g, int N, int T) {
    const int e    = GATHER ? blockIdx.z : 0;
    const int rows = GATHER ? g_cnt[e] : T;
    const int row0 = blockIdx.y * 128;
    if (row0 >= rows) return;
    const int col0 = blockIdx.x * 64;
    const size_t woff = (size_t)e * H_ * N;
    const bf16* Wgh = Wgh_g + woff; const bf16* Wgl = Wgl_g + woff;
    const bf16* Wuh = Wuh_g + woff; const bf16* Wul = Wul_g + woff;
    bf16* Ph = GATHER ? (Ph_g + (size_t)e * TMAX * N) : Ph_g;
    bf16* Pl = GATHER ? (Pl_g + (size_t)e * TMAX * N) : Pl_g;

    extern __shared__ char smem[];
    uint32_t sb = smem_u32(smem);
    const int tid = threadIdx.x, wid = tid >> 5, lane = tid & 31;
    int*   s_tok = (int*)(smem + SM_TOK);
    float* s_wt  = (float*)(smem + SM_WT);

    if (tid < 128) {
        int slot = row0 + tid;
        int cs0 = slot < rows ? slot : rows - 1;
        if (GATHER) { s_tok[tid] = g_tok[e * TMAX + cs0]; s_wt[tid] = g_wt[e * TMAX + cs0]; }
        else        { s_tok[tid] = cs0; }
    }
    __syncthreads();

    const int a_row = tid >> 1, a_half = tid & 1;
    const bf16* a_src = (a_half ? Xl : Xh) + (size_t)s_tok[a_row] * H_;
    const uint32_t a_dst_row = a_row * 128 + a_half * 64;
    const int b_tile = tid >> 6;                 // 0=GH 1=GL 2=UH 3=UL
    const int b_r    = (tid >> 1) & 31;
    const int b_part = tid & 1;
    const bf16* b_src = (b_tile == 0 ? Wgh : b_tile == 1 ? Wgl : b_tile == 2 ? Wuh : Wul)
                        + (size_t)b_r * N + col0 + b_part * 32;
    const uint32_t b_dst_row = b_tile * 4096 + b_r * 128 + b_part * 64;

    const int wm = wid & 3, wn = wid >> 2;
    const int a_r = wm * 32 + (lane & 15);
    const uint32_t xorA = (a_r & 7) << 4;
    const uint32_t hi16 = (lane >> 4) * 16;
    const int bfr = lane & 15;
    const uint32_t xorB = (bfr & 7) << 4;

    float accg[2][4][4] = {}, accu[2][4][4] = {};

    const int NCH = H_ / 32;
    // prologue: stages 0 and 1
#pragma unroll
    for (int s = 0; s < 2; s++) {
        uint32_t st = sb + SM_TILES + s * STAGE_BYTES;
        const bf16* as = a_src + s * 32;
        const bf16* bs = b_src + (size_t)s * 32 * N;
#pragma unroll
        for (int i = 0; i < 4; i++) {
            cp16(st + sw128(a_dst_row + i * 16), as + i * 8);
            cp16(st + SM_B_OFF + sw128(b_dst_row + i * 16), bs + i * 8);
        }
        CP_COMMIT();
    }

    int cs = 0;
    for (int ch = 0; ch < NCH; ch++) {
        if (ch + 2 < NCH) {
            int ls = cs + 2; if (ls >= N_STAGES) ls -= N_STAGES;
            const int k0 = (ch + 2) * 32;
            uint32_t st = sb + SM_TILES + ls * STAGE_BYTES;
            const bf16* as = a_src + k0;
            const bf16* bs = b_src + (size_t)k0 * N;
#pragma unroll
            for (int i = 0; i < 4; i++) {
                cp16(st + sw128(a_dst_row + i * 16), as + i * 8);
                cp16(st + SM_B_OFF + sw128(b_dst_row + i * 16), bs + i * 8);
            }
            CP_COMMIT();
            CP_WAIT(2);
        } else if (ch + 1 < NCH) {
            CP_WAIT(1);
        } else {
            CP_WAIT(0);
        }
        __syncthreads();

        uint32_t st  = sb + SM_TILES + cs * STAGE_BYTES;
        uint32_t bGH = st + SM_B_OFF, bGL = bGH + 4096;
        uint32_t bUH = bGL + 4096,    bUL = bUH + 4096;
#pragma unroll
        for (int ks = 0; ks < 2; ks++) {
            const uint32_t kb = ks * 32;
            uint32_t Ah[2][4], Al[2][4];
#pragma unroll
            for (int mi = 0; mi < 2; mi++) {
                uint32_t rowb = (uint32_t)(a_r + mi * 16) * 128;
                ldsm4(st + rowb + ((kb + hi16) ^ xorA), Ah[mi]);
                ldsm4(st + rowb + ((64 + kb + hi16) ^ xorA), Al[mi]);
            }
            const uint32_t rb = (uint32_t)(ks * 16 + bfr) * 128;
            // fragment double-buffer over 4 groups: (G,q0)(U,q0)(G,q1)(U,q1)
            uint32_t bh[2][4], bl[2][4];
            {
                uint32_t c0 = (wn * 64 + hi16) ^ xorB;
                ldsm4t(bGH + rb + c0, bh[0]);
                ldsm4t(bGL + rb + c0, bl[0]);
            }
            int cur = 0;
#pragma unroll
            for (int g = 0; g < 4; g++) {
                if (g < 3) {
                    const int gn = g + 1;
                    const int qn = gn >> 1, mn = gn & 1;
                    uint32_t c = (wn * 64 + qn * 32 + hi16) ^ xorB;
                    ldsm4t((mn ? bUH : bGH) + rb + c, bh[cur ^ 1]);
                    ldsm4t((mn ? bUL : bGL) + rb + c, bl[cur ^ 1]);
                }
                const int q = g >> 1, m = g & 1;
#pragma unroll
                for (int mi = 0; mi < 2; mi++)
#pragma unroll
                    for (int sub = 0; sub < 2; sub++) {
                        float* d = m ? accu[mi][q * 2 + sub] : accg[mi][q * 2 + sub];
                        mma16816(d, Ah[mi], bh[cur] + sub * 2);
                        mma16816(d, Ah[mi], bl[cur] + sub * 2);
                        mma16816(d, Al[mi], bh[cur] + sub * 2);
                    }
                cur ^= 1;
            }
        }
        __syncthreads();
        if (++cs >= N_STAGES) cs = 0;
    }

    // epilogue: silu(g)*u*w -> P hi/lo planes
#pragma unroll
    for (int mi = 0; mi < 2; mi++)
#pragma unroll
        for (int half = 0; half < 2; half++) {
            int mrow = wm * 32 + mi * 16 + (lane >> 2) + half * 8;
            int slot = row0 + mrow;
            if (slot < rows) {
                float wgt = GATHER ? s_wt[mrow] : 1.f;
#pragma unroll
                for (int nj = 0; nj < 4; nj++) {
                    float g0 = accg[mi][nj][half * 2],     u0 = accu[mi][nj][half * 2];
                    float g1 = accg[mi][nj][half * 2 + 1], u1 = accu[mi][nj][half * 2 + 1];
                    float v0 = (g0 / (1.f + __expf(-g0))) * u0 * wgt;
                    float v1 = (g1 / (1.f + __expf(-g1))) * u1 * wgt;
                    uint32_t hi, lo;
                    splitpair(v0, v1, hi, lo);
                    int n = col0 + wn * 32 + nj * 8 + (lane & 3) * 2;
                    size_t off = (size_t)slot * N + n;
                    *(uint32_t*)(Ph + off) = hi;
                    *(uint32_t*)(Pl + off) = lo;
                }
            }
        }
}

// ===== down: out (+)= P @ Wd — CTA 128m x 128n, k-chunk 32, 3-stage, frag prefetch =====
template <bool GATHER>
__global__ void __launch_bounds__(256, 2)
down_mma(const bf16* __restrict__ Ph_g, const bf16* __restrict__ Pl_g,
         const bf16* __restrict__ Wdh_g, const bf16* __restrict__ Wdl_g,
         float* __restrict__ out, int Kd, int T) {
    const int e    = GATHER ? blockIdx.z : 0;
    const int rows = GATHER ? g_cnt[e] : T;
    const int row0 = blockIdx.y * 128;
    if (row0 >= rows) return;
    const int col0 = blockIdx.x * 128;
    const size_t woff = (size_t)e * Kd * H_;
    const bf16* Wdh = Wdh_g + woff;
    const bf16* Wdl = Wdl_g + woff;
    const bf16* Ph = GATHER ? (Ph_g + (size_t)e * TMAX * Kd) : Ph_g;
    const bf16* Pl = GATHER ? (Pl_g + (size_t)e * TMAX * Kd) : Pl_g;

    extern __shared__ char smem[];
    uint32_t sb = smem_u32(smem);
    const int tid = threadIdx.x, wid = tid >> 5, lane = tid & 31;
    int* s_tok  = (int*)(smem + SM_TOK);
    int* s_slot = (int*)(smem + SM_WT);

    if (tid < 128) {
        int slot = row0 + tid;
        int cs0 = slot < rows ? slot : rows - 1;
        s_slot[tid] = cs0;
        s_tok[tid]  = GATHER ? g_tok[e * TMAX + cs0] : cs0;
    }
    __syncthreads();

    const int a_row = tid >> 1, a_half = tid & 1;
    const bf16* a_src = (a_half ? Pl : Ph) + (size_t)s_slot[a_row] * Kd;
    const uint32_t a_dst_row = a_row * 128 + a_half * 64;
    const int b_tile = tid >> 6;                 // (half<<1)|plane
    const int b_half = b_tile >> 1, b_plane = b_tile & 1;
    const int b_r    = (tid >> 1) & 31;
    const int b_part = tid & 1;
    const bf16* b_src = (b_plane ? Wdl : Wdh)
                        + (size_t)b_r * H_ + col0 + b_half * 64 + b_part * 32;
    const uint32_t b_dst_row = b_tile * 4096 + b_r * 128 + b_part * 64;

    const int wm = wid & 3, wn = wid >> 2;
    const int a_r = wm * 32 + (lane & 15);
    const uint32_t xorA = (a_r & 7) << 4;
    const uint32_t hi16 = (lane >> 4) * 16;
    const int bfr = lane & 15;
    const uint32_t xorB = (bfr & 7) << 4;

    float acc[2][8][4] = {};

    const int NCH = Kd / 32;
#pragma unroll
    for (int s = 0; s < 2; s++) {
        uint32_t st = sb + SM_TILES + s * STAGE_BYTES;
        const bf16* as = a_src + s * 32;
        const bf16* bs = b_src + (size_t)s * 32 * H_;
#pragma unroll
        for (int i = 0; i < 4; i++) {
            cp16(st + sw128(a_dst_row + i * 16), as + i * 8);
            cp16(st + SM_B_OFF + sw128(b_dst_row + i * 16), bs + i * 8);
        }
        CP_COMMIT();
    }

    int cs = 0;
    for (int ch = 0; ch < NCH; ch++) {
        if (ch + 2 < NCH) {
            int ls = cs + 2; if (ls >= N_STAGES) ls -= N_STAGES;
            const int k0 = (ch + 2) * 32;
            uint32_t st = sb + SM_TILES + ls * STAGE_BYTES;
            const bf16* as = a_src + k0;
            const bf16* bs = b_src + (size_t)k0 * H_;
#pragma unroll
            for (int i = 0; i < 4; i++) {
                cp16(st + sw128(a_dst_row + i * 16), as + i * 8);
                cp16(st + SM_B_OFF + sw128(b_dst_row + i * 16), bs + i * 8);
            }
            CP_COMMIT();
            CP_WAIT(2);
        } else if (ch + 1 < NCH) {
            CP_WAIT(1);
        } else {
            CP_WAIT(0);
        }
        __syncthreads();

        uint32_t st = sb + SM_TILES + cs * STAGE_BYTES;
        uint32_t bH = st + SM_B_OFF + wn * 8192;
        uint32_t bL = bH + 4096;
#pragma unroll
        for (int ks = 0; ks < 2; ks++) {
            const uint32_t kb = ks * 32;
            uint32_t Ah[2][4], Al[2][4];
#pragma unroll
            for (int mi = 0; mi < 2; mi++) {
                uint32_t rowb = (uint32_t)(a_r + mi * 16) * 128;
                ldsm4(st + rowb + ((kb + hi16) ^ xorA), Ah[mi]);
                ldsm4(st + rowb + ((64 + kb + hi16) ^ xorA), Al[mi]);
            }
            const uint32_t rb = (uint32_t)(ks * 16 + bfr) * 128;
            uint32_t bh[2][4], bl[2][4];
            {
                uint32_t c0 = hi16 ^ xorB;
                ldsm4t(bH + rb + c0, bh[0]);
                ldsm4t(bL + rb + c0, bl[0]);
            }
            int cur = 0;
#pragma unroll
            for (int q = 0; q < 4; q++) {
                if (q < 3) {
                    uint32_t c = ((q + 1) * 32 + hi16) ^ xorB;
                    ldsm4t(bH + rb + c, bh[cur ^ 1]);
                    ldsm4t(bL + rb + c, bl[cur ^ 1]);
                }
#pragma unroll
                for (int mi = 0; mi < 2; mi++)
#pragma unroll
                    for (int sub = 0; sub < 2; sub++) {
                        float* d = acc[mi][q * 2 + sub];
                        mma16816(d, Ah[mi], bh[cur] + sub * 2);
                        mma16816(d, Ah[mi], bl[cur] + sub * 2);
                        mma16816(d, Al[mi], bh[cur] + sub * 2);
                    }
                cur ^= 1;
            }
        }
        __syncthreads();
        if (++cs >= N_STAGES) cs = 0;
    }

#pragma unroll
    for (int mi = 0; mi < 2; mi++)
#pragma unroll
        for (int half = 0; half < 2; half++) {
            int mrow = wm * 32 + mi * 16 + (lane >> 2) + half * 8;
            int slot = row0 + mrow;
            if (slot < rows) {
                float* orow = out + (size_t)s_tok[mrow] * H_;
#pragma unroll
                for (int nj = 0; nj < 8; nj++) {
                    int n = col0 + wn * 64 + nj * 8 + (lane & 3) * 2;
                    float v0 = acc[mi][nj][half * 2], v1 = acc[mi][nj][half * 2 + 1];
                    if (GATHER) {
                        atomicAdd(&orow[n], v0);
                        atomicAdd(&orow[n + 1], v1);
                    } else {
                        *(float2*)(orow + n) = make_float2(v0, v1);
                    }
                }
            }
        }
}

// ---------------- launch ----------------
extern "C" void kernel_launch(void* const* d_in, const int* in_sizes, int n_in,
                              void* d_out, int out_size) {
    const float* X   = (const float*)d_in[0];
    const float* gw  = (const float*)d_in[1];
    const float* Wg  = (const float*)d_in[2];
    const float* Wu  = (const float*)d_in[3];
    const float* Wd  = (const float*)d_in[4];
    const float* sWg = (const float*)d_in[5];
    const float* sWu = (const float*)d_in[6];
    const float* sWd = (const float*)d_in[7];
    float* out = (float*)d_out;

    int T = in_sizes[0] / H_;   // 2048

    static bool attr_done = false;
    if (!attr_done) {
        cudaFuncSetAttribute(up_mma<false>,   cudaFuncAttributeMaxDynamicSharedMemorySize, SMEM_BYTES);
        cudaFuncSetAttribute(up_mma<true>,    cudaFuncAttributeMaxDynamicSharedMemorySize, SMEM_BYTES);
        cudaFuncSetAttribute(down_mma<false>, cudaFuncAttributeMaxDynamicSharedMemorySize, SMEM_BYTES);
        cudaFuncSetAttribute(down_mma<true>,  cudaFuncAttributeMaxDynamicSharedMemorySize, SMEM_BYTES);
        attr_done = true;
    }

    bf16 *Xh, *Xl, *sWgh, *sWgl, *sWuh, *sWul, *sWdh, *sWdl;
    bf16 *Wgh, *Wgl, *Wuh, *Wul, *Wdh, *Wdl, *Psh, *Psl, *Prh, *Prl;
    cudaGetSymbolAddress((void**)&Xh,  g_Xh);   cudaGetSymbolAddress((void**)&Xl,  g_Xl);
    cudaGetSymbolAddress((void**)&sWgh, g_sWgh); cudaGetSymbolAddress((void**)&sWgl, g_sWgl);
    cudaGetSymbolAddress((void**)&sWuh, g_sWuh); cudaGetSymbolAddress((void**)&sWul, g_sWul);
    cudaGetSymbolAddress((void**)&sWdh, g_sWdh); cudaGetSymbolAddress((void**)&sWdl, g_sWdl);
    cudaGetSymbolAddress((void**)&Wgh, g_Wgh);  cudaGetSymbolAddress((void**)&Wgl, g_Wgl);
    cudaGetSymbolAddress((void**)&Wuh, g_Wuh);  cudaGetSymbolAddress((void**)&Wul, g_Wul);
    cudaGetSymbolAddress((void**)&Wdh, g_Wdh);  cudaGetSymbolAddress((void**)&Wdl, g_Wdl);
    cudaGetSymbolAddress((void**)&Psh, g_Psh);  cudaGetSymbolAddress((void**)&Psl, g_Psl);
    cudaGetSymbolAddress((void**)&Prh, g_Prh);  cudaGetSymbolAddress((void**)&Prl, g_Prl);

    zero_cnt_kernel<<<1, 32>>>();
    router_kernel<<<(T + 7) / 8, 256>>>(X, gw, T);

    const int CB = 2048, CT = 256;
    convert_split<<<CB, CT>>>(X,   Xh,   Xl,   (size_t)T * H_ / 4);
    convert_split<<<CB, CT>>>(sWg, sWgh, sWgl, (size_t)H_ * IS_ / 4);
    convert_split<<<CB, CT>>>(sWu, sWuh, sWul, (size_t)H_ * IS_ / 4);
    convert_split<<<CB, CT>>>(sWd, sWdh, sWdl, (size_t)IS_ * H_ / 4);
    convert_split<<<CB, CT>>>(Wg,  Wgh,  Wgl,  (size_t)E_ * H_ * IM_ / 4);
    convert_split<<<CB, CT>>>(Wu,  Wuh,  Wul,  (size_t)E_ * H_ * IM_ / 4);
    convert_split<<<CB, CT>>>(Wd,  Wdh,  Wdl,  (size_t)E_ * IM_ * H_ / 4);

    int ry = (T + 127) / 128;
    up_mma<false><<<dim3(IS_ / 64, ry), 256, SMEM_BYTES>>>(
        Xh, Xl, sWgh, sWgl, sWuh, sWul, Psh, Psl, IS_, T);
    up_mma<true><<<dim3(IM_ / 64, ry, E_), 256, SMEM_BYTES>>>(
        Xh, Xl, Wgh, Wgl, Wuh, Wul, Prh, Prl, IM_, T);
    down_mma<false><<<dim3(H_ / 128, ry), 256, SMEM_BYTES>>>(
        Psh, Psl, sWdh, sWdl, out, IS_, T);
    down_mma<true><<<dim3(H_ / 128, ry, E_), 256, SMEM_BYTES>>>(
        Prh, Prl, Wdh, Wdl, out, IM_, T);
}